// round 5
// baseline (speedup 1.0000x reference)
#include <cuda_runtime.h>
#include <cuda_bf16.h>
#include <math.h>
#include <stdint.h>

// ---------------- problem constants ----------------
#define BB   8
#define HH   32
#define WW   32
#define DIM  768
#define NH   6
#define NP   4
#define DV   384
#define DH   64
#define HID  192
#define LQ   5376
#define LIN  1024
#define NTOK (BB*LQ)    // 43008
#define NFEAT (BB*LIN)  // 8192
#define OA_LD 96        // padded projection width

// ---------------- scratch (device globals) ----------------
__device__ __nv_bfloat16 g_v[NFEAT * DV];
__device__ float g_oa[NTOK * OA_LD];
__device__ float g_h1[NTOK * HID];
__device__ __nv_bfloat16 g_lnq[NTOK * DIM];
__device__ __nv_bfloat16 g_lnf[NFEAT * DIM];
__device__ __nv_bfloat16 g_lnx[NTOK * DIM];
__device__ __nv_bfloat16 g_attnb[NTOK * DV];
__device__ __nv_bfloat16 g_h2b[NTOK * HID];
__device__ __nv_bfloat16 g_wval[DV * DIM];
__device__ __nv_bfloat16 g_wout[DIM * DV];
__device__ __nv_bfloat16 g_wproj[OA_LD * DIM];
__device__ __nv_bfloat16 g_wfc1[HID * DIM];
__device__ __nv_bfloat16 g_wfc2[DIM * HID];
__device__ float g_bproj[OA_LD];

// ---------------- PTX helpers (sm_80+ portable) ----------------
__device__ __forceinline__ uint32_t smem_u32(const void* p) {
    uint32_t a;
    asm("{ .reg .u64 t; cvta.to.shared.u64 t, %1; cvt.u32.u64 %0, t; }" : "=r"(a) : "l"(p));
    return a;
}
__device__ __forceinline__ void cp16(uint32_t s, const void* g) {
    asm volatile("cp.async.cg.shared.global [%0], [%1], 16;" :: "r"(s), "l"(g));
}
#define CP_COMMIT() asm volatile("cp.async.commit_group;" ::: "memory")
#define CP_WAIT(n)  asm volatile("cp.async.wait_group %0;" :: "n"(n) : "memory")

__device__ __forceinline__ void ldmx4(uint32_t* r, uint32_t addr) {
    asm volatile("ldmatrix.sync.aligned.m8n8.x4.shared.b16 {%0,%1,%2,%3}, [%4];"
        : "=r"(r[0]), "=r"(r[1]), "=r"(r[2]), "=r"(r[3]) : "r"(addr));
}
__device__ __forceinline__ void mma16816(float* c, const uint32_t* a, const uint32_t* b) {
    asm volatile(
        "mma.sync.aligned.m16n8k16.row.col.f32.bf16.bf16.f32 "
        "{%0,%1,%2,%3}, {%4,%5,%6,%7}, {%8,%9}, {%0,%1,%2,%3};"
        : "+f"(c[0]), "+f"(c[1]), "+f"(c[2]), "+f"(c[3])
        : "r"(a[0]), "r"(a[1]), "r"(a[2]), "r"(a[3]), "r"(b[0]), "r"(b[1]));
}

// ---------------- one-pass LayerNorm + bf16 cast (reg-cached row) -------
__global__ __launch_bounds__(256) void ln_cast(const float* __restrict__ X,
                                               const float* __restrict__ g,
                                               const float* __restrict__ bta,
                                               __nv_bfloat16* __restrict__ Y)
{
    const int row = blockIdx.x;
    const int tid = threadIdx.x;
    const float* x = X + (size_t)row * DIM;
    float v[3];
    #pragma unroll
    for (int j = 0; j < 3; j++) v[j] = x[tid + j * 256];
    float s = v[0] + v[1] + v[2];
    float q = v[0] * v[0] + v[1] * v[1] + v[2] * v[2];
    // warp reduce
    #pragma unroll
    for (int o = 16; o > 0; o >>= 1) {
        s += __shfl_xor_sync(0xffffffffu, s, o);
        q += __shfl_xor_sync(0xffffffffu, q, o);
    }
    __shared__ float ws[8], wq[8];
    if ((tid & 31) == 0) { ws[tid >> 5] = s; wq[tid >> 5] = q; }
    __syncthreads();
    __shared__ float s_m, s_r;
    if (tid < 8) {
        float ts = ws[tid], tq = wq[tid];
        #pragma unroll
        for (int o = 4; o > 0; o >>= 1) {
            ts += __shfl_xor_sync(0xffu, ts, o);
            tq += __shfl_xor_sync(0xffu, tq, o);
        }
        if (tid == 0) {
            float mean = ts * (1.f / DIM);
            float var  = tq * (1.f / DIM) - mean * mean;
            s_m = mean;
            s_r = rsqrtf(var + 1e-6f);
        }
    }
    __syncthreads();
    const float m = s_m, r = s_r;
    __nv_bfloat16* y = Y + (size_t)row * DIM;
    #pragma unroll
    for (int j = 0; j < 3; j++) {
        int i = tid + j * 256;
        y[i] = __float2bfloat16((v[j] - m) * r * g[i] + bta[i]);
    }
}

// ---------------- one-shot weight prep ----------------
#define SEG0 (DIM*DV)
#define SEG1 (DV*DIM)
#define SEG2 (DIM*HID)
#define SEG3 (HID*DIM)
#define SEG4 (OA_LD*DIM)
#define PREP_TOT (SEG0+SEG1+SEG2+SEG3+SEG4+OA_LD)
__global__ __launch_bounds__(256) void prep_weights(
    const float* __restrict__ W_val, const float* __restrict__ W_out,
    const float* __restrict__ fc1_w, const float* __restrict__ fc2_w,
    const float* __restrict__ Woff, const float* __restrict__ Wattn,
    const float* __restrict__ boff, const float* __restrict__ battn,
    __nv_bfloat16* __restrict__ wval, __nv_bfloat16* __restrict__ wout,
    __nv_bfloat16* __restrict__ wfc1, __nv_bfloat16* __restrict__ wfc2,
    __nv_bfloat16* __restrict__ wproj, float* __restrict__ bproj)
{
    int gid = blockIdx.x * 256 + threadIdx.x;
    if (gid < SEG0) {
        int k = gid / DV, n = gid % DV;
        wval[(size_t)n * DIM + k] = __float2bfloat16(W_val[gid]);
        return;
    }
    gid -= SEG0;
    if (gid < SEG1) {
        int k = gid / DIM, n = gid % DIM;
        wout[(size_t)n * DV + k] = __float2bfloat16(W_out[gid]);
        return;
    }
    gid -= SEG1;
    if (gid < SEG2) {
        int k = gid / HID, n = gid % HID;
        wfc1[(size_t)n * DIM + k] = __float2bfloat16(fc1_w[gid]);
        return;
    }
    gid -= SEG2;
    if (gid < SEG3) {
        int k = gid / DIM, n = gid % DIM;
        wfc2[(size_t)n * HID + k] = __float2bfloat16(fc2_w[gid]);
        return;
    }
    gid -= SEG3;
    if (gid < SEG4) {
        int n = gid / DIM, k = gid % DIM;
        float v = 0.f;
        if (n < 48)      v = Woff[(size_t)k * 48 + n];
        else if (n < 72) v = Wattn[(size_t)k * 24 + (n - 48)];
        wproj[gid] = __float2bfloat16(v);
        return;
    }
    gid -= SEG4;
    if (gid < OA_LD)
        bproj[gid] = (gid < 48) ? boff[gid] : ((gid < 72) ? battn[gid - 48] : 0.f);
}

// ---------------- bf16 mma.sync GEMM, BK=64, 2-stage, frag dbl-buffer ---
// CTA tile 128x96, 256 threads = 8 warps (4m x 2n), warp 32x48.
#define BM 128
#define BN 96
#define BK 64
#define KPAD 72    // halves per smem row (144B stride -> conflict-free ldmatrix)
#define STG ((BM + BN) * KPAD)
#define GEMM_SMEM (2 * STG * 2)

template<bool RES, bool ACC, bool OUTBF>
__global__ __launch_bounds__(256) void gemm_mma(
    const __nv_bfloat16* __restrict__ A,   // [M,K] row-major
    const __nv_bfloat16* __restrict__ Bt,  // [N,K] row-major
    const float* __restrict__ bias,        // [N]
    const float* __restrict__ R,           // [M,N] residual (RES)
    void* __restrict__ Cv, int M, int N, int K)
{
    extern __shared__ __nv_bfloat16 dsm[];

    const int tid  = threadIdx.x;
    const int wid  = tid >> 5, lane = tid & 31;
    const int wm   = wid >> 1, wn = wid & 1;
    const int bm   = blockIdx.y * BM, bn = blockIdx.x * BN;

    float acc[2][6][4];
    #pragma unroll
    for (int i = 0; i < 2; i++)
        #pragma unroll
        for (int j = 0; j < 6; j++)
            #pragma unroll
            for (int v = 0; v < 4; v++) acc[i][j][v] = 0.f;

    const uint32_t uS = smem_u32(dsm);

    // cp.async coordinates: each thread covers col-chunk (tid&7)*16B of rows tid>>3 + 32*i
    const int crow = tid >> 3;
    const int ccol = (tid & 7) * 8;   // halves

    // ldmatrix lane-address components
    const int a_r = wm * 32 + (lane & 15);
    const int a_c = (lane >> 4) * 8;
    const int b_r = wn * 48 + ((lane >> 4) & 1) * 8 + (lane & 7);
    const int b_c = ((lane >> 3) & 1) * 8;

    const int nk = K >> 6;

    // ---- prologue: stage 0 ----
    {
        const uint32_t baseA = uS;
        const uint32_t baseB = uS + (uint32_t)(BM * KPAD) * 2;
        #pragma unroll
        for (int i = 0; i < 4; i++) {
            int rr = crow + i * 32;
            cp16(baseA + (uint32_t)(rr * KPAD + ccol) * 2, A + (size_t)(bm + rr) * K + ccol);
        }
        #pragma unroll
        for (int i = 0; i < 3; i++) {
            int rr = crow + i * 32;
            cp16(baseB + (uint32_t)(rr * KPAD + ccol) * 2, Bt + (size_t)(bn + rr) * K + ccol);
        }
        CP_COMMIT();
    }

    for (int c = 0; c < nk; c++) {
        CP_WAIT(0);
        __syncthreads();

        // issue next chunk into alternate buffer (overlaps with compute below)
        if (c + 1 < nk) {
            const int k0 = (c + 1) << 6;
            const uint32_t baseA = uS + (uint32_t)(((c + 1) & 1) * STG) * 2;
            const uint32_t baseB = baseA + (uint32_t)(BM * KPAD) * 2;
            #pragma unroll
            for (int i = 0; i < 4; i++) {
                int rr = crow + i * 32;
                cp16(baseA + (uint32_t)(rr * KPAD + ccol) * 2,
                     A + (size_t)(bm + rr) * K + k0 + ccol);
            }
            #pragma unroll
            for (int i = 0; i < 3; i++) {
                int rr = crow + i * 32;
                cp16(baseB + (uint32_t)(rr * KPAD + ccol) * 2,
                     Bt + (size_t)(bn + rr) * K + k0 + ccol);
            }
            CP_COMMIT();
        }

        // ---- compute chunk c (4 kk steps, fragment double-buffered) ----
        const uint32_t bA = uS + (uint32_t)((c & 1) * STG) * 2;
        const uint32_t bB = bA + (uint32_t)(BM * KPAD) * 2;

        uint32_t af[2][2][4];
        uint32_t bf[2][6][2];
        // load kk=0 fragments
        #pragma unroll
        for (int mt = 0; mt < 2; mt++)
            ldmx4(af[0][mt], bA + (uint32_t)((a_r + mt * 16) * KPAD + a_c) * 2);
        #pragma unroll
        for (int g = 0; g < 3; g++) {
            uint32_t r[4];
            ldmx4(r, bB + (uint32_t)((b_r + g * 16) * KPAD + b_c) * 2);
            bf[0][g * 2 + 0][0] = r[0]; bf[0][g * 2 + 0][1] = r[1];
            bf[0][g * 2 + 1][0] = r[2]; bf[0][g * 2 + 1][1] = r[3];
        }
        #pragma unroll
        for (int kk = 0; kk < 4; kk++) {
            const int cur = kk & 1, nxt = cur ^ 1;
            if (kk < 3) {
                const int kc = (kk + 1) * 16;
                #pragma unroll
                for (int mt = 0; mt < 2; mt++)
                    ldmx4(af[nxt][mt], bA + (uint32_t)((a_r + mt * 16) * KPAD + kc + a_c) * 2);
                #pragma unroll
                for (int g = 0; g < 3; g++) {
                    uint32_t r[4];
                    ldmx4(r, bB + (uint32_t)((b_r + g * 16) * KPAD + kc + b_c) * 2);
                    bf[nxt][g * 2 + 0][0] = r[0]; bf[nxt][g * 2 + 0][1] = r[1];
                    bf[nxt][g * 2 + 1][0] = r[2]; bf[nxt][g * 2 + 1][1] = r[3];
                }
            }
            #pragma unroll
            for (int mt = 0; mt < 2; mt++)
                #pragma unroll
                for (int nt = 0; nt < 6; nt++)
                    mma16816(acc[mt][nt], af[cur][mt], bf[cur][nt]);
        }
        __syncthreads();
    }

    // ---- epilogue ----
    const int er = bm + wm * 32 + (lane >> 2);
    const int ec = bn + wn * 48 + (lane & 3) * 2;
    #pragma unroll
    for (int mt = 0; mt < 2; mt++) {
        #pragma unroll
        for (int nt = 0; nt < 6; nt++) {
            const int row0 = er + mt * 16;
            const int col  = ec + nt * 8;
            float2 bv = *(const float2*)&bias[col];
            size_t off0 = (size_t)row0 * N + col;
            size_t off1 = off0 + (size_t)8 * N;
            float2 o0, o1;
            o0.x = acc[mt][nt][0] + bv.x; o0.y = acc[mt][nt][1] + bv.y;
            o1.x = acc[mt][nt][2] + bv.x; o1.y = acc[mt][nt][3] + bv.y;
            if (OUTBF) {
                __nv_bfloat16* Cb = (__nv_bfloat16*)Cv;
                __nv_bfloat162 h0, h1;
                h0.x = __float2bfloat16(o0.x); h0.y = __float2bfloat16(o0.y);
                h1.x = __float2bfloat16(o1.x); h1.y = __float2bfloat16(o1.y);
                *(__nv_bfloat162*)&Cb[off0] = h0;
                *(__nv_bfloat162*)&Cb[off1] = h1;
            } else {
                float* C = (float*)Cv;
                if (RES) {
                    float2 r0 = *(const float2*)&R[off0];
                    float2 r1 = *(const float2*)&R[off1];
                    o0.x += r0.x; o0.y += r0.y; o1.x += r1.x; o1.y += r1.y;
                }
                if (ACC) {
                    float2 c0 = *(const float2*)&C[off0];
                    float2 c1 = *(const float2*)&C[off1];
                    o0.x += c0.x; o0.y += c0.y; o1.x += c1.x; o1.y += c1.y;
                }
                *(float2*)&C[off0] = o0;
                *(float2*)&C[off1] = o1;
            }
        }
    }
}

// ---------------- sampling: softmax + bilinear gather (single barrier) --
__global__ __launch_bounds__(192) void sample_kernel(
    const float* __restrict__ oa,       // [NTOK, 96]
    const float* __restrict__ refp,
    __nv_bfloat16* __restrict__ attn_bf)
{
    __shared__ int   sidx[24][4];
    __shared__ float swt[24][4];

    const int t = blockIdx.x;
    const int b = t / LQ;
    const int tid = threadIdx.x;
    const float* oarow = oa + (size_t)t * OA_LD;

    if (tid < 24) {
        const int h = tid >> 2, p = tid & 3;
        // per-thread softmax for this head (redundant across the head's 4 threads)
        float l0 = oarow[48 + h * 4 + 0], l1 = oarow[48 + h * 4 + 1];
        float l2 = oarow[48 + h * 4 + 2], l3 = oarow[48 + h * 4 + 3];
        float mx = fmaxf(fmaxf(l0, l1), fmaxf(l2, l3));
        float e0 = expf(l0 - mx), e1 = expf(l1 - mx);
        float e2 = expf(l2 - mx), e3 = expf(l3 - mx);
        float inv = 1.f / (e0 + e1 + e2 + e3);
        float ep = (p == 0) ? e0 : (p == 1) ? e1 : (p == 2) ? e2 : e3;
        const float a = ep * inv;

        float rx = refp[(size_t)t * 2 + 0];
        float ry = refp[(size_t)t * 2 + 1];
        float lx = rx + oarow[h * 8 + p * 2 + 0] * (1.f / (float)WW);
        float ly = ry + oarow[h * 8 + p * 2 + 1] * (1.f / (float)HH);
        float x = lx * (float)WW - 0.5f;
        float y = ly * (float)HH - 0.5f;
        float x0f = floorf(x), y0f = floorf(y);
        float wx = x - x0f, wy = y - y0f;
        int x0 = (int)x0f, y0 = (int)y0f;
        #pragma unroll
        for (int c = 0; c < 4; c++) {
            int dx = c & 1, dy = c >> 1;
            int xi = x0 + dx, yi = y0 + dy;
            bool ok = (xi >= 0) && (xi < WW) && (yi >= 0) && (yi < HH);
            sidx[tid][c] = ok ? (yi * WW + xi) : -1;
            float wgt = (dx ? wx : 1.f - wx) * (dy ? wy : 1.f - wy);
            swt[tid][c] = ok ? wgt * a : 0.f;
        }
    }
    __syncthreads();

    {
        const int d = tid * 2;         // 0..382
        const int h = d >> 6;
        float ax = 0.f, ay = 0.f;
        const __nv_bfloat16* vb = g_v + (size_t)b * LIN * DV;
        #pragma unroll
        for (int p = 0; p < 4; p++) {
            int hp = h * 4 + p;
            #pragma unroll
            for (int c = 0; c < 4; c++) {
                int idx = sidx[hp][c];
                float wv = swt[hp][c];
                if (idx >= 0) {
                    __nv_bfloat162 v = *(const __nv_bfloat162*)&vb[(size_t)idx * DV + d];
                    ax += wv * __bfloat162float(v.x);
                    ay += wv * __bfloat162float(v.y);
                }
            }
        }
        __nv_bfloat162 o;
        o.x = __float2bfloat16(ax); o.y = __float2bfloat16(ay);
        *(__nv_bfloat162*)&attn_bf[(size_t)t * DV + d] = o;
    }
}

// ---------------- depthwise 3x3 conv + exact GELU -> bf16 ---------------
__global__ __launch_bounds__(256) void dwconv_gelu(
    const float* __restrict__ hin, const float* __restrict__ dww,
    const float* __restrict__ dwb, __nv_bfloat16* __restrict__ hout)
{
    int gid = blockIdx.x * 256 + threadIdx.x;
    if (gid >= NTOK * HID) return;
    int ch = gid % HID;
    int t  = (gid / HID) % LQ;
    int b  = gid / (HID * LQ);

    int base, hh, ww;
    if (t < 4096)      { base = 0;    hh = 64; ww = 64; }
    else if (t < 5120) { base = 4096; hh = 32; ww = 32; }
    else               { base = 5120; hh = 16; ww = 16; }
    int tl = t - base;
    int rr = tl / ww, cc = tl % ww;

    const float* in = hin + ((size_t)b * LQ + base) * HID + ch;
    float acc = dwb[ch];
    #pragma unroll
    for (int ky = 0; ky < 3; ky++) {
        int y = rr + ky - 1;
        if (y < 0 || y >= hh) continue;
        #pragma unroll
        for (int kx = 0; kx < 3; kx++) {
            int x = cc + kx - 1;
            if (x < 0 || x >= ww) continue;
            acc += in[(size_t)(y * ww + x) * HID] * dww[(ky * 3 + kx) * HID + ch];
        }
    }
    float ge = 0.5f * acc * (1.f + erff(acc * 0.70710678118654752440f));
    hout[gid] = __float2bfloat16(ge);
}

// ---------------- host launcher ----------------
extern "C" void kernel_launch(void* const* d_in, const int* in_sizes, int n_in,
                              void* d_out, int out_size)
{
    const float* query  = (const float*)d_in[0];
    const float* refp   = (const float*)d_in[1];
    const float* feat   = (const float*)d_in[2];
    const float* qn_g   = (const float*)d_in[5];
    const float* qn_b   = (const float*)d_in[6];
    const float* fn_g   = (const float*)d_in[7];
    const float* fn_b   = (const float*)d_in[8];
    const float* W_off  = (const float*)d_in[9];
    const float* b_off  = (const float*)d_in[10];
    const float* W_attn = (const float*)d_in[11];
    const float* b_attn = (const float*)d_in[12];
    const float* W_val  = (const float*)d_in[13];
    const float* b_val  = (const float*)d_in[14];
    const float* W_out  = (const float*)d_in[15];
    const float* b_out  = (const float*)d_in[16];
    const float* ffn_g  = (const float*)d_in[17];
    const float* ffn_b  = (const float*)d_in[18];
    const float* fc1_w  = (const float*)d_in[19];
    const float* fc1_b  = (const float*)d_in[20];
    const float* dw_w   = (const float*)d_in[21];
    const float* dw_b   = (const float*)d_in[22];
    const float* fc2_w  = (const float*)d_in[23];
    const float* fc2_b  = (const float*)d_in[24];
    float* out = (float*)d_out;

    float *poa, *ph1, *pbproj;
    __nv_bfloat16 *pv, *plnq, *plnf, *plnx, *pattnb, *ph2b;
    __nv_bfloat16 *pwval, *pwout, *pwproj, *pwfc1, *pwfc2;
    cudaGetSymbolAddress((void**)&pv,     g_v);
    cudaGetSymbolAddress((void**)&poa,    g_oa);
    cudaGetSymbolAddress((void**)&ph1,    g_h1);
    cudaGetSymbolAddress((void**)&pbproj, g_bproj);
    cudaGetSymbolAddress((void**)&plnq,   g_lnq);
    cudaGetSymbolAddress((void**)&plnf,   g_lnf);
    cudaGetSymbolAddress((void**)&plnx,   g_lnx);
    cudaGetSymbolAddress((void**)&pattnb, g_attnb);
    cudaGetSymbolAddress((void**)&ph2b,   g_h2b);
    cudaGetSymbolAddress((void**)&pwval,  g_wval);
    cudaGetSymbolAddress((void**)&pwout,  g_wout);
    cudaGetSymbolAddress((void**)&pwproj, g_wproj);
    cudaGetSymbolAddress((void**)&pwfc1,  g_wfc1);
    cudaGetSymbolAddress((void**)&pwfc2,  g_wfc2);

    cudaFuncSetAttribute(gemm_mma<false,false,true>,
        cudaFuncAttributeMaxDynamicSharedMemorySize, GEMM_SMEM);
    cudaFuncSetAttribute(gemm_mma<false,false,false>,
        cudaFuncAttributeMaxDynamicSharedMemorySize, GEMM_SMEM);
    cudaFuncSetAttribute(gemm_mma<true,false,false>,
        cudaFuncAttributeMaxDynamicSharedMemorySize, GEMM_SMEM);
    cudaFuncSetAttribute(gemm_mma<false,true,false>,
        cudaFuncAttributeMaxDynamicSharedMemorySize, GEMM_SMEM);

    // LN + bf16 casts
    ln_cast<<<NTOK, 256>>>(query, qn_g, qn_b, plnq);
    ln_cast<<<NFEAT, 256>>>(feat, fn_g, fn_b, plnf);

    // fused weight prep
    prep_weights<<<(PREP_TOT + 255) / 256, 256>>>(
        W_val, W_out, fc1_w, fc2_w, W_off, W_attn, b_off, b_attn,
        pwval, pwout, pwfc1, pwfc2, pwproj, pbproj);

    // v = LN(feat) @ W_val + b_val           (8192 x 384, K=768) -> bf16
    gemm_mma<false, false, true><<<dim3(DV / BN, NFEAT / BM), 256, GEMM_SMEM>>>(
        plnf, pwval, b_val, nullptr, pv, NFEAT, DV, DIM);

    // oa = LN(q) @ [W_off|W_attn|pad] + b    (43008 x 96, K=768)
    gemm_mma<false, false, false><<<dim3(OA_LD / BN, NTOK / BM), 256, GEMM_SMEM>>>(
        plnq, pwproj, pbproj, nullptr, poa, NTOK, OA_LD, DIM);

    // softmax + bilinear gather -> attn (bf16)
    sample_kernel<<<NTOK, 192>>>(poa, refp, pattnb);

    // x = attn @ W_out + b_out + query       (43008 x 768, K=384)
    gemm_mma<true, false, false><<<dim3(DIM / BN, NTOK / BM), 256, GEMM_SMEM>>>(
        pattnb, pwout, b_out, query, out, NTOK, DIM, DV);

    // FFN
    ln_cast<<<NTOK, 256>>>(out, ffn_g, ffn_b, plnx);

    // h1 = LN(x) @ fc1_w + fc1_b             (43008 x 192, K=768)
    gemm_mma<false, false, false><<<dim3(HID / BN, NTOK / BM), 256, GEMM_SMEM>>>(
        plnx, pwfc1, fc1_b, nullptr, ph1, NTOK, HID, DIM);

    // depthwise conv + gelu -> bf16
    dwconv_gelu<<<(NTOK * HID) / 256, 256>>>(ph1, dw_w, dw_b, ph2b);

    // out += h2 @ fc2_w + fc2_b              (43008 x 768, K=192)
    gemm_mma<false, true, false><<<dim3(DIM / BN, NTOK / BM), 256, GEMM_SMEM>>>(
        ph2b, pwfc2, fc2_b, nullptr, out, NTOK, DIM, HID);
}

// round 6
// speedup vs baseline: 1.4332x; 1.4332x over previous
#include <cuda_runtime.h>
#include <cuda_bf16.h>
#include <math.h>
#include <stdint.h>

// ---------------- problem constants ----------------
#define BB   8
#define HH   32
#define WW   32
#define DIM  768
#define NH   6
#define NP   4
#define DV   384
#define DH   64
#define HID  192
#define LQ   5376
#define LIN  1024
#define NTOK (BB*LQ)    // 43008
#define NFEAT (BB*LIN)  // 8192
#define OA_LD 96        // padded projection width

// ---------------- scratch (device globals) ----------------
__device__ __nv_bfloat16 g_v[NFEAT * DV];
__device__ float g_oa[NTOK * OA_LD];
__device__ __nv_bfloat16 g_h1b[NTOK * HID];
__device__ __nv_bfloat16 g_lnq[NTOK * DIM];
__device__ __nv_bfloat16 g_lnf[NFEAT * DIM];
__device__ __nv_bfloat16 g_lnx[NTOK * DIM];
__device__ __nv_bfloat16 g_attnb[NTOK * DV];
__device__ __nv_bfloat16 g_h2b[NTOK * HID];
__device__ __nv_bfloat16 g_wval[DV * DIM];
__device__ __nv_bfloat16 g_wout[DIM * DV];
__device__ __nv_bfloat16 g_wproj[OA_LD * DIM];
__device__ __nv_bfloat16 g_wfc1[HID * DIM];
__device__ __nv_bfloat16 g_wfc2[DIM * HID];
__device__ float g_bproj[OA_LD];

// ---------------- PTX helpers (sm_80+ portable) ----------------
__device__ __forceinline__ uint32_t smem_u32(const void* p) {
    uint32_t a;
    asm("{ .reg .u64 t; cvta.to.shared.u64 t, %1; cvt.u32.u64 %0, t; }" : "=r"(a) : "l"(p));
    return a;
}
__device__ __forceinline__ void cp16(uint32_t s, const void* g) {
    asm volatile("cp.async.cg.shared.global [%0], [%1], 16;" :: "r"(s), "l"(g));
}
#define CP_COMMIT() asm volatile("cp.async.commit_group;" ::: "memory")
#define CP_WAIT(n)  asm volatile("cp.async.wait_group %0;" :: "n"(n) : "memory")

__device__ __forceinline__ void ldmx4(uint32_t* r, uint32_t addr) {
    asm volatile("ldmatrix.sync.aligned.m8n8.x4.shared.b16 {%0,%1,%2,%3}, [%4];"
        : "=r"(r[0]), "=r"(r[1]), "=r"(r[2]), "=r"(r[3]) : "r"(addr));
}
__device__ __forceinline__ void mma16816(float* c, const uint32_t* a, const uint32_t* b) {
    asm volatile(
        "mma.sync.aligned.m16n8k16.row.col.f32.bf16.bf16.f32 "
        "{%0,%1,%2,%3}, {%4,%5,%6,%7}, {%8,%9}, {%0,%1,%2,%3};"
        : "+f"(c[0]), "+f"(c[1]), "+f"(c[2]), "+f"(c[3])
        : "r"(a[0]), "r"(a[1]), "r"(a[2]), "r"(a[3]), "r"(b[0]), "r"(b[1]));
}

// ---------------- one-pass LayerNorm + bf16 cast (reg-cached row) -------
__global__ __launch_bounds__(256) void ln_cast(const float* __restrict__ X,
                                               const float* __restrict__ g,
                                               const float* __restrict__ bta,
                                               __nv_bfloat16* __restrict__ Y)
{
    const int row = blockIdx.x;
    const int tid = threadIdx.x;
    const float* x = X + (size_t)row * DIM;
    float v[3];
    #pragma unroll
    for (int j = 0; j < 3; j++) v[j] = x[tid + j * 256];
    float s = v[0] + v[1] + v[2];
    float q = v[0] * v[0] + v[1] * v[1] + v[2] * v[2];
    #pragma unroll
    for (int o = 16; o > 0; o >>= 1) {
        s += __shfl_xor_sync(0xffffffffu, s, o);
        q += __shfl_xor_sync(0xffffffffu, q, o);
    }
    __shared__ float ws[8], wq[8];
    if ((tid & 31) == 0) { ws[tid >> 5] = s; wq[tid >> 5] = q; }
    __syncthreads();
    __shared__ float s_m, s_r;
    if (tid < 8) {
        float ts = ws[tid], tq = wq[tid];
        #pragma unroll
        for (int o = 4; o > 0; o >>= 1) {
            ts += __shfl_xor_sync(0xffu, ts, o);
            tq += __shfl_xor_sync(0xffu, tq, o);
        }
        if (tid == 0) {
            float mean = ts * (1.f / DIM);
            float var  = tq * (1.f / DIM) - mean * mean;
            s_m = mean;
            s_r = rsqrtf(var + 1e-6f);
        }
    }
    __syncthreads();
    const float m = s_m, r = s_r;
    __nv_bfloat16* y = Y + (size_t)row * DIM;
    #pragma unroll
    for (int j = 0; j < 3; j++) {
        int i = tid + j * 256;
        y[i] = __float2bfloat16((v[j] - m) * r * g[i] + bta[i]);
    }
}

// ---------------- one-shot weight prep ----------------
#define SEG0 (DIM*DV)
#define SEG1 (DV*DIM)
#define SEG2 (DIM*HID)
#define SEG3 (HID*DIM)
#define SEG4 (OA_LD*DIM)
#define PREP_TOT (SEG0+SEG1+SEG2+SEG3+SEG4+OA_LD)
__global__ __launch_bounds__(256) void prep_weights(
    const float* __restrict__ W_val, const float* __restrict__ W_out,
    const float* __restrict__ fc1_w, const float* __restrict__ fc2_w,
    const float* __restrict__ Woff, const float* __restrict__ Wattn,
    const float* __restrict__ boff, const float* __restrict__ battn,
    __nv_bfloat16* __restrict__ wval, __nv_bfloat16* __restrict__ wout,
    __nv_bfloat16* __restrict__ wfc1, __nv_bfloat16* __restrict__ wfc2,
    __nv_bfloat16* __restrict__ wproj, float* __restrict__ bproj)
{
    int gid = blockIdx.x * 256 + threadIdx.x;
    if (gid < SEG0) {
        int k = gid / DV, n = gid % DV;
        wval[(size_t)n * DIM + k] = __float2bfloat16(W_val[gid]);
        return;
    }
    gid -= SEG0;
    if (gid < SEG1) {
        int k = gid / DIM, n = gid % DIM;
        wout[(size_t)n * DV + k] = __float2bfloat16(W_out[gid]);
        return;
    }
    gid -= SEG1;
    if (gid < SEG2) {
        int k = gid / HID, n = gid % HID;
        wfc1[(size_t)n * DIM + k] = __float2bfloat16(fc1_w[gid]);
        return;
    }
    gid -= SEG2;
    if (gid < SEG3) {
        int k = gid / DIM, n = gid % DIM;
        wfc2[(size_t)n * HID + k] = __float2bfloat16(fc2_w[gid]);
        return;
    }
    gid -= SEG3;
    if (gid < SEG4) {
        int n = gid / DIM, k = gid % DIM;
        float v = 0.f;
        if (n < 48)      v = Woff[(size_t)k * 48 + n];
        else if (n < 72) v = Wattn[(size_t)k * 24 + (n - 48)];
        wproj[gid] = __float2bfloat16(v);
        return;
    }
    gid -= SEG4;
    if (gid < OA_LD)
        bproj[gid] = (gid < 48) ? boff[gid] : ((gid < 72) ? battn[gid - 48] : 0.f);
}

// ---------------- bf16 mma.sync GEMM (R3 shape): BK=32, 2-stage ---------
// CTA tile 128x96, 256 threads = 8 warps (4m x 2n), warp 32x48.
// One __syncthreads per chunk (write into buf b at iter c is ordered after
// every thread's compute of buf b at iter c-2 via the top barrier).
#define BM 128
#define BN 96
#define APAD 40
#define STG ((BM + BN) * APAD)
#define GEMM_SMEM (2 * STG * 2)

template<bool RES, bool ACC, bool OUTBF>
__global__ __launch_bounds__(256) void gemm_mma(
    const __nv_bfloat16* __restrict__ A,   // [M,K] row-major
    const __nv_bfloat16* __restrict__ Bt,  // [N,K] row-major
    const float* __restrict__ bias,        // [N]
    const float* __restrict__ R,           // [M,N] residual (RES)
    void* __restrict__ Cv, int M, int N, int K)
{
    extern __shared__ __nv_bfloat16 dsm[];

    const int tid  = threadIdx.x;
    const int wid  = tid >> 5, lane = tid & 31;
    const int wm   = wid >> 1, wn = wid & 1;
    const int bm   = blockIdx.y * BM, bn = blockIdx.x * BN;

    float acc[2][6][4];
    #pragma unroll
    for (int i = 0; i < 2; i++)
        #pragma unroll
        for (int j = 0; j < 6; j++)
            #pragma unroll
            for (int v = 0; v < 4; v++) acc[i][j][v] = 0.f;

    const uint32_t uS = smem_u32(dsm);

    // cp.async chunk coordinates (BK=32: 4 chunks of 8 halves per row)
    const int ar0 = tid >> 2, ac0 = (tid & 3) * 8;
    const int ar1 = ar0 + 64;
    const int br0 = tid >> 2;
    const int br1 = br0 + 64;    // valid when tid < 128

    // ldmatrix lane-address components
    const int a_r = wm * 32 + (lane & 15);
    const int a_c = (lane >> 4) * 8;
    const int b_r = wn * 48 + ((lane >> 4) & 1) * 8 + (lane & 7);
    const int b_c = ((lane >> 3) & 1) * 8;

    const int nk = K >> 5;

    // ---- prologue: chunk 0 into buffer 0 ----
    {
        const uint32_t baseA = uS;
        const uint32_t baseB = uS + (uint32_t)(BM * APAD) * 2;
        cp16(baseA + (uint32_t)(ar0 * APAD + ac0) * 2, A  + (size_t)(bm + ar0) * K + ac0);
        cp16(baseA + (uint32_t)(ar1 * APAD + ac0) * 2, A  + (size_t)(bm + ar1) * K + ac0);
        cp16(baseB + (uint32_t)(br0 * APAD + ac0) * 2, Bt + (size_t)(bn + br0) * K + ac0);
        if (tid < 128)
            cp16(baseB + (uint32_t)(br1 * APAD + ac0) * 2, Bt + (size_t)(bn + br1) * K + ac0);
        CP_COMMIT();
    }

    for (int c = 0; c < nk; c++) {
        CP_WAIT(0);
        __syncthreads();

        if (c + 1 < nk) {
            const int k0 = (c + 1) << 5;
            const uint32_t baseA = uS + (uint32_t)(((c + 1) & 1) * STG) * 2;
            const uint32_t baseB = baseA + (uint32_t)(BM * APAD) * 2;
            cp16(baseA + (uint32_t)(ar0 * APAD + ac0) * 2,
                 A + (size_t)(bm + ar0) * K + k0 + ac0);
            cp16(baseA + (uint32_t)(ar1 * APAD + ac0) * 2,
                 A + (size_t)(bm + ar1) * K + k0 + ac0);
            cp16(baseB + (uint32_t)(br0 * APAD + ac0) * 2,
                 Bt + (size_t)(bn + br0) * K + k0 + ac0);
            if (tid < 128)
                cp16(baseB + (uint32_t)(br1 * APAD + ac0) * 2,
                     Bt + (size_t)(bn + br1) * K + k0 + ac0);
            CP_COMMIT();
        }

        // ---- compute chunk c ----
        const uint32_t bA = uS + (uint32_t)((c & 1) * STG) * 2;
        const uint32_t bB = bA + (uint32_t)(BM * APAD) * 2;
        #pragma unroll
        for (int kk = 0; kk < 2; kk++) {
            uint32_t afr[2][4];
            #pragma unroll
            for (int mt = 0; mt < 2; mt++)
                ldmx4(afr[mt], bA + (uint32_t)((a_r + mt * 16) * APAD + kk * 16 + a_c) * 2);
            uint32_t bfr[6][2];
            #pragma unroll
            for (int g = 0; g < 3; g++) {
                uint32_t r[4];
                ldmx4(r, bB + (uint32_t)((b_r + g * 16) * APAD + kk * 16 + b_c) * 2);
                bfr[g * 2 + 0][0] = r[0]; bfr[g * 2 + 0][1] = r[1];
                bfr[g * 2 + 1][0] = r[2]; bfr[g * 2 + 1][1] = r[3];
            }
            #pragma unroll
            for (int mt = 0; mt < 2; mt++)
                #pragma unroll
                for (int nt = 0; nt < 6; nt++)
                    mma16816(acc[mt][nt], afr[mt], bfr[nt]);
        }
    }

    // ---- epilogue ----
    const int er = bm + wm * 32 + (lane >> 2);
    const int ec = bn + wn * 48 + (lane & 3) * 2;
    #pragma unroll
    for (int mt = 0; mt < 2; mt++) {
        #pragma unroll
        for (int nt = 0; nt < 6; nt++) {
            const int row0 = er + mt * 16;
            const int col  = ec + nt * 8;
            float2 bv = *(const float2*)&bias[col];
            size_t off0 = (size_t)row0 * N + col;
            size_t off1 = off0 + (size_t)8 * N;
            float2 o0, o1;
            o0.x = acc[mt][nt][0] + bv.x; o0.y = acc[mt][nt][1] + bv.y;
            o1.x = acc[mt][nt][2] + bv.x; o1.y = acc[mt][nt][3] + bv.y;
            if (OUTBF) {
                __nv_bfloat16* Cb = (__nv_bfloat16*)Cv;
                __nv_bfloat162 h0, h1;
                h0.x = __float2bfloat16(o0.x); h0.y = __float2bfloat16(o0.y);
                h1.x = __float2bfloat16(o1.x); h1.y = __float2bfloat16(o1.y);
                *(__nv_bfloat162*)&Cb[off0] = h0;
                *(__nv_bfloat162*)&Cb[off1] = h1;
            } else {
                float* C = (float*)Cv;
                if (RES) {
                    float2 r0 = *(const float2*)&R[off0];
                    float2 r1 = *(const float2*)&R[off1];
                    o0.x += r0.x; o0.y += r0.y; o1.x += r1.x; o1.y += r1.y;
                }
                if (ACC) {
                    float2 c0 = *(const float2*)&C[off0];
                    float2 c1 = *(const float2*)&C[off1];
                    o0.x += c0.x; o0.y += c0.y; o1.x += c1.x; o1.y += c1.y;
                }
                *(float2*)&C[off0] = o0;
                *(float2*)&C[off1] = o1;
            }
        }
    }
}

// ---------------- sampling: softmax + bilinear gather (single barrier) --
__global__ __launch_bounds__(192) void sample_kernel(
    const float* __restrict__ oa,       // [NTOK, 96]
    const float* __restrict__ refp,
    __nv_bfloat16* __restrict__ attn_bf)
{
    __shared__ int   sidx[24][4];
    __shared__ float swt[24][4];

    const int t = blockIdx.x;
    const int b = t / LQ;
    const int tid = threadIdx.x;
    const float* oarow = oa + (size_t)t * OA_LD;

    if (tid < 24) {
        const int h = tid >> 2, p = tid & 3;
        float l0 = oarow[48 + h * 4 + 0], l1 = oarow[48 + h * 4 + 1];
        float l2 = oarow[48 + h * 4 + 2], l3 = oarow[48 + h * 4 + 3];
        float mx = fmaxf(fmaxf(l0, l1), fmaxf(l2, l3));
        float e0 = expf(l0 - mx), e1 = expf(l1 - mx);
        float e2 = expf(l2 - mx), e3 = expf(l3 - mx);
        float inv = 1.f / (e0 + e1 + e2 + e3);
        float ep = (p == 0) ? e0 : (p == 1) ? e1 : (p == 2) ? e2 : e3;
        const float a = ep * inv;

        float rx = refp[(size_t)t * 2 + 0];
        float ry = refp[(size_t)t * 2 + 1];
        float lx = rx + oarow[h * 8 + p * 2 + 0] * (1.f / (float)WW);
        float ly = ry + oarow[h * 8 + p * 2 + 1] * (1.f / (float)HH);
        float x = lx * (float)WW - 0.5f;
        float y = ly * (float)HH - 0.5f;
        float x0f = floorf(x), y0f = floorf(y);
        float wx = x - x0f, wy = y - y0f;
        int x0 = (int)x0f, y0 = (int)y0f;
        #pragma unroll
        for (int c = 0; c < 4; c++) {
            int dx = c & 1, dy = c >> 1;
            int xi = x0 + dx, yi = y0 + dy;
            bool ok = (xi >= 0) && (xi < WW) && (yi >= 0) && (yi < HH);
            sidx[tid][c] = ok ? (yi * WW + xi) : -1;
            float wgt = (dx ? wx : 1.f - wx) * (dy ? wy : 1.f - wy);
            swt[tid][c] = ok ? wgt * a : 0.f;
        }
    }
    __syncthreads();

    {
        const int d = tid * 2;         // 0..382
        const int h = d >> 6;
        float ax = 0.f, ay = 0.f;
        const __nv_bfloat16* vb = g_v + (size_t)b * LIN * DV;
        #pragma unroll
        for (int p = 0; p < 4; p++) {
            int hp = h * 4 + p;
            #pragma unroll
            for (int c = 0; c < 4; c++) {
                int idx = sidx[hp][c];
                float wv = swt[hp][c];
                if (idx >= 0) {
                    __nv_bfloat162 v = *(const __nv_bfloat162*)&vb[(size_t)idx * DV + d];
                    ax += wv * __bfloat162float(v.x);
                    ay += wv * __bfloat162float(v.y);
                }
            }
        }
        __nv_bfloat162 o;
        o.x = __float2bfloat16(ax); o.y = __float2bfloat16(ay);
        *(__nv_bfloat162*)&attn_bf[(size_t)t * DV + d] = o;
    }
}

// ---------------- depthwise 3x3 conv (bf16 in) + exact GELU -> bf16 -----
__global__ __launch_bounds__(256) void dwconv_gelu(
    const __nv_bfloat16* __restrict__ hin, const float* __restrict__ dww,
    const float* __restrict__ dwb, __nv_bfloat16* __restrict__ hout)
{
    int gid = blockIdx.x * 256 + threadIdx.x;
    if (gid >= NTOK * HID) return;
    int ch = gid % HID;
    int t  = (gid / HID) % LQ;
    int b  = gid / (HID * LQ);

    int base, hh, ww;
    if (t < 4096)      { base = 0;    hh = 64; ww = 64; }
    else if (t < 5120) { base = 4096; hh = 32; ww = 32; }
    else               { base = 5120; hh = 16; ww = 16; }
    int tl = t - base;
    int rr = tl / ww, cc = tl % ww;

    const __nv_bfloat16* in = hin + ((size_t)b * LQ + base) * HID + ch;
    float acc = dwb[ch];
    #pragma unroll
    for (int ky = 0; ky < 3; ky++) {
        int y = rr + ky - 1;
        if (y < 0 || y >= hh) continue;
        #pragma unroll
        for (int kx = 0; kx < 3; kx++) {
            int x = cc + kx - 1;
            if (x < 0 || x >= ww) continue;
            acc += __bfloat162float(in[(size_t)(y * ww + x) * HID])
                 * dww[(ky * 3 + kx) * HID + ch];
        }
    }
    float ge = 0.5f * acc * (1.f + erff(acc * 0.70710678118654752440f));
    hout[gid] = __float2bfloat16(ge);
}

// ---------------- host launcher ----------------
extern "C" void kernel_launch(void* const* d_in, const int* in_sizes, int n_in,
                              void* d_out, int out_size)
{
    const float* query  = (const float*)d_in[0];
    const float* refp   = (const float*)d_in[1];
    const float* feat   = (const float*)d_in[2];
    const float* qn_g   = (const float*)d_in[5];
    const float* qn_b   = (const float*)d_in[6];
    const float* fn_g   = (const float*)d_in[7];
    const float* fn_b   = (const float*)d_in[8];
    const float* W_off  = (const float*)d_in[9];
    const float* b_off  = (const float*)d_in[10];
    const float* W_attn = (const float*)d_in[11];
    const float* b_attn = (const float*)d_in[12];
    const float* W_val  = (const float*)d_in[13];
    const float* b_val  = (const float*)d_in[14];
    const float* W_out  = (const float*)d_in[15];
    const float* b_out  = (const float*)d_in[16];
    const float* ffn_g  = (const float*)d_in[17];
    const float* ffn_b  = (const float*)d_in[18];
    const float* fc1_w  = (const float*)d_in[19];
    const float* fc1_b  = (const float*)d_in[20];
    const float* dw_w   = (const float*)d_in[21];
    const float* dw_b   = (const float*)d_in[22];
    const float* fc2_w  = (const float*)d_in[23];
    const float* fc2_b  = (const float*)d_in[24];
    float* out = (float*)d_out;

    float *poa, *pbproj;
    __nv_bfloat16 *pv, *ph1b, *plnq, *plnf, *plnx, *pattnb, *ph2b;
    __nv_bfloat16 *pwval, *pwout, *pwproj, *pwfc1, *pwfc2;
    cudaGetSymbolAddress((void**)&pv,     g_v);
    cudaGetSymbolAddress((void**)&poa,    g_oa);
    cudaGetSymbolAddress((void**)&ph1b,   g_h1b);
    cudaGetSymbolAddress((void**)&pbproj, g_bproj);
    cudaGetSymbolAddress((void**)&plnq,   g_lnq);
    cudaGetSymbolAddress((void**)&plnf,   g_lnf);
    cudaGetSymbolAddress((void**)&plnx,   g_lnx);
    cudaGetSymbolAddress((void**)&pattnb, g_attnb);
    cudaGetSymbolAddress((void**)&ph2b,   g_h2b);
    cudaGetSymbolAddress((void**)&pwval,  g_wval);
    cudaGetSymbolAddress((void**)&pwout,  g_wout);
    cudaGetSymbolAddress((void**)&pwproj, g_wproj);
    cudaGetSymbolAddress((void**)&pwfc1,  g_wfc1);
    cudaGetSymbolAddress((void**)&pwfc2,  g_wfc2);

    cudaFuncSetAttribute(gemm_mma<false,false,true>,
        cudaFuncAttributeMaxDynamicSharedMemorySize, GEMM_SMEM);
    cudaFuncSetAttribute(gemm_mma<false,false,false>,
        cudaFuncAttributeMaxDynamicSharedMemorySize, GEMM_SMEM);
    cudaFuncSetAttribute(gemm_mma<true,false,false>,
        cudaFuncAttributeMaxDynamicSharedMemorySize, GEMM_SMEM);
    cudaFuncSetAttribute(gemm_mma<false,true,false>,
        cudaFuncAttributeMaxDynamicSharedMemorySize, GEMM_SMEM);

    // LN + bf16 casts
    ln_cast<<<NTOK, 256>>>(query, qn_g, qn_b, plnq);
    ln_cast<<<NFEAT, 256>>>(feat, fn_g, fn_b, plnf);

    // fused weight prep
    prep_weights<<<(PREP_TOT + 255) / 256, 256>>>(
        W_val, W_out, fc1_w, fc2_w, W_off, W_attn, b_off, b_attn,
        pwval, pwout, pwfc1, pwfc2, pwproj, pbproj);

    // v = LN(feat) @ W_val + b_val           (8192 x 384, K=768) -> bf16
    gemm_mma<false, false, true><<<dim3(DV / BN, NFEAT / BM), 256, GEMM_SMEM>>>(
        plnf, pwval, b_val, nullptr, pv, NFEAT, DV, DIM);

    // oa = LN(q) @ [W_off|W_attn|pad] + b    (43008 x 96, K=768)
    gemm_mma<false, false, false><<<dim3(OA_LD / BN, NTOK / BM), 256, GEMM_SMEM>>>(
        plnq, pwproj, pbproj, nullptr, poa, NTOK, OA_LD, DIM);

    // softmax + bilinear gather -> attn (bf16)
    sample_kernel<<<NTOK, 192>>>(poa, refp, pattnb);

    // x = attn @ W_out + b_out + query       (43008 x 768, K=384)
    gemm_mma<true, false, false><<<dim3(DIM / BN, NTOK / BM), 256, GEMM_SMEM>>>(
        pattnb, pwout, b_out, query, out, NTOK, DIM, DV);

    // FFN
    ln_cast<<<NTOK, 256>>>(out, ffn_g, ffn_b, plnx);

    // h1 = LN(x) @ fc1_w + fc1_b             (43008 x 192, K=768) -> bf16
    gemm_mma<false, false, true><<<dim3(HID / BN, NTOK / BM), 256, GEMM_SMEM>>>(
        plnx, pwfc1, fc1_b, nullptr, ph1b, NTOK, HID, DIM);

    // depthwise conv + gelu -> bf16
    dwconv_gelu<<<(NTOK * HID) / 256, 256>>>(ph1b, dw_w, dw_b, ph2b);

    // out += h2 @ fc2_w + fc2_b              (43008 x 768, K=192)
    gemm_mma<false, true, false><<<dim3(DIM / BN, NTOK / BM), 256, GEMM_SMEM>>>(
        ph2b, pwfc2, fc2_b, nullptr, out, NTOK, DIM, HID);
}